// round 1
// baseline (speedup 1.0000x reference)
#include <cuda_runtime.h>

#define N_NODES 20000
#define N_EDGES 640000

// ---------------- scratch (static device memory, no allocation) ----------------
__device__ float g_y0 [N_NODES * 32];        // y0[n][u]
__device__ float g_y1t[N_NODES * 3 * 32];    // y1t[n][m][u] = y1[n,u,m]
__device__ float g_y2t[N_NODES * 5 * 32];    // y2t[n][m][u] = y2[n,u,m]
__device__ float g_sc [3 * N_NODES * 32];    // sc[h][n][w]
__device__ float g_mid[N_NODES * 96];        // segment-summed messages

__device__ __forceinline__ float silu_f(float x) {
    return x / (1.0f + __expf(-x));
}

// ---------------- Kernel 1a: y0/y1/y2 node pre-linear, zero mid ----------------
// warp per node, lane = output channel v
__global__ void k1a_kernel(const float* __restrict__ x,
                           const float* __restrict__ W1_0,
                           const float* __restrict__ W1_1,
                           const float* __restrict__ W1_2)
{
    __shared__ __align__(16) float w0s[1024], w1s[1024], w2s[1024];
    int t = threadIdx.x;
    for (int i = t; i < 1024; i += blockDim.x) {
        w0s[i] = W1_0[i]; w1s[i] = W1_1[i]; w2s[i] = W1_2[i];
    }
    __syncthreads();

    int lane = t & 31;
    int n = (int)((blockIdx.x * blockDim.x + t) >> 5);
    if (n >= N_NODES) return;

    const float* xr = x + (size_t)n * 288;
    float x0r = xr[lane];
    float x1r[3], x2r[5];
#pragma unroll
    for (int m = 0; m < 3; m++) x1r[m] = xr[32 + lane * 3 + m];
#pragma unroll
    for (int m = 0; m < 5; m++) x2r[m] = xr[128 + lane * 5 + m];

    float a0 = 0.f;
    float a1[3] = {0.f, 0.f, 0.f};
    float a2[5] = {0.f, 0.f, 0.f, 0.f, 0.f};
#pragma unroll
    for (int u = 0; u < 32; u++) {
        float xv0 = __shfl_sync(0xffffffffu, x0r, u);
        a0 = fmaf(xv0, w0s[u * 32 + lane], a0);
#pragma unroll
        for (int m = 0; m < 3; m++) {
            float xv = __shfl_sync(0xffffffffu, x1r[m], u);
            a1[m] = fmaf(xv, w1s[u * 32 + lane], a1[m]);
        }
#pragma unroll
        for (int m = 0; m < 5; m++) {
            float xv = __shfl_sync(0xffffffffu, x2r[m], u);
            a2[m] = fmaf(xv, w2s[u * 32 + lane], a2[m]);
        }
    }
    const float inv = 0.17677669529663687f; // 1/sqrt(32)
    g_y0[n * 32 + lane] = a0 * inv;
#pragma unroll
    for (int m = 0; m < 3; m++) g_y1t[(n * 3 + m) * 32 + lane] = a1[m] * inv;
#pragma unroll
    for (int m = 0; m < 5; m++) g_y2t[(n * 5 + m) * 32 + lane] = a2[m] * inv;

    // zero mid for the edge-scatter pass
    g_mid[n * 96 + lane]      = 0.f;
    g_mid[n * 96 + 32 + lane] = 0.f;
    g_mid[n * 96 + 64 + lane] = 0.f;
}

// ---------------- Kernel 1b: self-connection sc ----------------
// sc[h,n,w] = sum_{u,v} x0[n,u] * na[n,v] * scW[h,u,v,w] / sqrt(128)
// warp per node, lane = w
__global__ void k1b_kernel(const float* __restrict__ x,
                           const float* __restrict__ na,
                           const float* __restrict__ scW)
{
    __shared__ __align__(16) float s[12288]; // 3*32*4*32 floats = 48KB
    int t = threadIdx.x;
    for (int i = t; i < 12288; i += blockDim.x) s[i] = scW[i];
    __syncthreads();

    int lane = t & 31;
    int n = (int)((blockIdx.x * blockDim.x + t) >> 5);
    if (n >= N_NODES) return;

    float x0r = x[(size_t)n * 288 + lane];
    float nar = (lane < 4) ? na[n * 4 + lane] : 0.f;
    float na0 = __shfl_sync(0xffffffffu, nar, 0);
    float na1 = __shfl_sync(0xffffffffu, nar, 1);
    float na2 = __shfl_sync(0xffffffffu, nar, 2);
    float na3 = __shfl_sync(0xffffffffu, nar, 3);

    float acc[3] = {0.f, 0.f, 0.f};
#pragma unroll
    for (int u = 0; u < 32; u++) {
        float x0u = __shfl_sync(0xffffffffu, x0r, u);
        float c0 = x0u * na0, c1 = x0u * na1, c2 = x0u * na2, c3 = x0u * na3;
#pragma unroll
        for (int h = 0; h < 3; h++) {
            const float* p = s + ((h * 32 + u) * 4) * 32 + lane;
            acc[h] = fmaf(c0, p[0],  acc[h]);
            acc[h] = fmaf(c1, p[32], acc[h]);
            acc[h] = fmaf(c2, p[64], acc[h]);
            acc[h] = fmaf(c3, p[96], acc[h]);
        }
    }
    const float invs = 0.08838834764831845f; // 1/sqrt(128)
#pragma unroll
    for (int h = 0; h < 3; h++)
        g_sc[h * (N_NODES * 32) + n * 32 + lane] = acc[h] * invs;
}

// ---------------- Kernel 2: fused edge MLP + gather + message + scatter ----------------
// warp per edge (grid-stride). lane = channel u. Per lane computes w[lane], w[32+lane], w[64+lane].
__global__ void k2_kernel(const float* __restrict__ ee,
                          const float* __restrict__ ea,
                          const int*   __restrict__ eidx,
                          const float* __restrict__ Wm0,
                          const float* __restrict__ Wm1)
{
    // Wm1 transposed: wm1t[c][k], row stride 68 floats (conflict-free LDS.128)
    __shared__ __align__(16) float wm1t[96 * 68];
    __shared__ __align__(16) float msgb[8][96];

    int t = threadIdx.x;
    for (int i = t; i < 64 * 96; i += blockDim.x) {
        int j = i / 96, c = i % 96;
        wm1t[c * 68 + j] = Wm1[i];
    }
    __syncthreads();

    int lane = t & 31;
    int wrp  = t >> 5;

    float wa[8], wb[8];
#pragma unroll
    for (int k = 0; k < 8; k++) {
        wa[k] = Wm0[k * 64 + lane];
        wb[k] = Wm0[k * 64 + 32 + lane];
    }

    const float inv8 = 0.35355339059327373f;  // 1/sqrt(8)
    const float invh = 0.125f;                // 1/sqrt(64)
    const float savg = 0.17677669529663687f;  // 1/sqrt(32)
    const float r3   = 0.5773502691896258f;   // 1/sqrt(3)
    const float r5   = 0.4472135954999579f;   // 1/sqrt(5)

    int warpid = blockIdx.x * (blockDim.x >> 5) + wrp;
    int nwarp  = gridDim.x * (blockDim.x >> 5);

    for (int e = warpid; e < N_EDGES; e += nwarp) {
        int sidx = __ldg(&eidx[e]);
        int didx = __ldg(&eidx[N_EDGES + e]);

        float eev = (lane < 8) ? __ldg(&ee[(size_t)e * 8 + lane]) : 0.f;
        float eav = (lane < 9) ? __ldg(&ea[(size_t)e * 9 + lane]) : 0.f;

        // ---- h = silu(ee @ Wm0 / sqrt(8)), h[lane] and h[32+lane] ----
        float ha = 0.f, hb = 0.f;
#pragma unroll
        for (int k = 0; k < 8; k++) {
            float ek = __shfl_sync(0xffffffffu, eev, k);
            ha = fmaf(ek, wa[k], ha);
            hb = fmaf(ek, wb[k], hb);
        }
        ha = silu_f(ha * inv8);
        hb = silu_f(hb * inv8);

        // ---- w = h @ Wm1 / 8 : three outputs per lane ----
        float acc0 = 0.f, acc1 = 0.f, acc2 = 0.f;
#pragma unroll
        for (int k = 0; k < 64; k += 4) {
            float hk0 = __shfl_sync(0xffffffffu, (k + 0 < 32) ? ha : hb, (k + 0) & 31);
            float hk1 = __shfl_sync(0xffffffffu, (k + 1 < 32) ? ha : hb, (k + 1) & 31);
            float hk2 = __shfl_sync(0xffffffffu, (k + 2 < 32) ? ha : hb, (k + 2) & 31);
            float hk3 = __shfl_sync(0xffffffffu, (k + 3 < 32) ? ha : hb, (k + 3) & 31);
            float4 q0 = *(const float4*)&wm1t[(lane)      * 68 + k];
            float4 q1 = *(const float4*)&wm1t[(32 + lane) * 68 + k];
            float4 q2 = *(const float4*)&wm1t[(64 + lane) * 68 + k];
            acc0 = fmaf(hk3, q0.w, fmaf(hk2, q0.z, fmaf(hk1, q0.y, fmaf(hk0, q0.x, acc0))));
            acc1 = fmaf(hk3, q1.w, fmaf(hk2, q1.z, fmaf(hk1, q1.y, fmaf(hk0, q1.x, acc1))));
            acc2 = fmaf(hk3, q2.w, fmaf(hk2, q2.z, fmaf(hk1, q2.y, fmaf(hk0, q2.x, acc2))));
        }

        // ---- gather source node features (L2-resident, coalesced per warp) ----
        float y0v = g_y0[(size_t)sidx * 32 + lane];
        float z1 = 0.f;
#pragma unroll
        for (int m = 0; m < 3; m++) {
            float Ym = __shfl_sync(0xffffffffu, eav, 1 + m);
            z1 = fmaf(Ym, g_y1t[((size_t)sidx * 3 + m) * 32 + lane], z1);
        }
        float z2 = 0.f;
#pragma unroll
        for (int m = 0; m < 5; m++) {
            float Ym = __shfl_sync(0xffffffffu, eav, 4 + m);
            z2 = fmaf(Ym, g_y2t[((size_t)sidx * 5 + m) * 32 + lane], z2);
        }
        float Y0 = __shfl_sync(0xffffffffu, eav, 0);

        float m0 = acc0 * invh * y0v * Y0 * savg;
        float m1 = acc1 * invh * z1 * r3 * savg;
        float m2 = acc2 * invh * z2 * r5 * savg;

        // ---- stage message and scatter with vector atomics ----
        msgb[wrp][lane]      = m0;
        msgb[wrp][32 + lane] = m1;
        msgb[wrp][64 + lane] = m2;
        __syncwarp();
        if (lane < 24) {
            float4 v = *(const float4*)&msgb[wrp][lane * 4];
            float* p = &g_mid[(size_t)didx * 96 + lane * 4];
            asm volatile("red.global.add.v4.f32 [%0], {%1,%2,%3,%4};"
                         :: "l"(p), "f"(v.x), "f"(v.y), "f"(v.z), "f"(v.w)
                         : "memory");
        }
        __syncwarp();
    }
}

// ---------------- Kernel 3: node finalize ----------------
// h_i = silu(mid[:, :K_i] @ lin2_i / sqrt(K_i) + sc[i]); warp per node, lane = output w
__global__ void k3_kernel(const float* __restrict__ l2_0,
                          const float* __restrict__ l2_1,
                          const float* __restrict__ l2_2,
                          float* __restrict__ out)
{
    __shared__ __align__(16) float s0[32 * 32];
    __shared__ __align__(16) float s1[64 * 32];
    __shared__ __align__(16) float s2[96 * 32];
    int t = threadIdx.x;
    for (int i = t; i < 1024; i += blockDim.x) s0[i] = l2_0[i];
    for (int i = t; i < 2048; i += blockDim.x) s1[i] = l2_1[i];
    for (int i = t; i < 3072; i += blockDim.x) s2[i] = l2_2[i];
    __syncthreads();

    int lane = t & 31;
    int n = (int)((blockIdx.x * blockDim.x + t) >> 5);
    if (n >= N_NODES) return;

    float m0 = g_mid[n * 96 + lane];
    float m1 = g_mid[n * 96 + 32 + lane];
    float m2 = g_mid[n * 96 + 64 + lane];

    float a0 = 0.f, a1 = 0.f, a2 = 0.f;
#pragma unroll
    for (int k = 0; k < 32; k++) {
        float mk = __shfl_sync(0xffffffffu, m0, k);
        a0 = fmaf(mk, s0[k * 32 + lane], a0);
        a1 = fmaf(mk, s1[k * 32 + lane], a1);
        a2 = fmaf(mk, s2[k * 32 + lane], a2);
    }
#pragma unroll
    for (int k = 0; k < 32; k++) {
        float mk = __shfl_sync(0xffffffffu, m1, k);
        a1 = fmaf(mk, s1[(32 + k) * 32 + lane], a1);
        a2 = fmaf(mk, s2[(32 + k) * 32 + lane], a2);
    }
#pragma unroll
    for (int k = 0; k < 32; k++) {
        float mk = __shfl_sync(0xffffffffu, m2, k);
        a2 = fmaf(mk, s2[(64 + k) * 32 + lane], a2);
    }

    const float i32 = 0.17677669529663687f;  // 1/sqrt(32)
    const float i64 = 0.125f;                // 1/sqrt(64)
    const float i96 = 0.10206207261596575f;  // 1/sqrt(96)

    float o0 = silu_f(fmaf(a0, i32, g_sc[                 n * 32 + lane]));
    float o1 = silu_f(fmaf(a1, i64, g_sc[N_NODES * 32   + n * 32 + lane]));
    float o2 = silu_f(fmaf(a2, i96, g_sc[2 * N_NODES * 32 + n * 32 + lane]));

    out[                  n * 32 + lane] = o0;
    out[N_NODES * 32    + n * 32 + lane] = o1;
    out[2 * N_NODES * 32 + n * 32 + lane] = o2;
}

// ---------------- launch ----------------
extern "C" void kernel_launch(void* const* d_in, const int* in_sizes, int n_in,
                              void* d_out, int out_size)
{
    const float* x      = (const float*)d_in[0];
    const float* na     = (const float*)d_in[1];
    const float* ee     = (const float*)d_in[2];
    const float* ea     = (const float*)d_in[3];
    const int*   eidx   = (const int*)  d_in[4];
    const float* W1_0   = (const float*)d_in[5];
    const float* W1_1   = (const float*)d_in[6];
    const float* W1_2   = (const float*)d_in[7];
    const float* Wm0    = (const float*)d_in[8];
    const float* Wm1    = (const float*)d_in[9];
    const float* l2_0   = (const float*)d_in[10];
    const float* l2_1   = (const float*)d_in[11];
    const float* l2_2   = (const float*)d_in[12];
    const float* scW    = (const float*)d_in[13];
    float* out = (float*)d_out;

    // 20000 nodes, warp per node, 8 warps/block
    k1a_kernel<<<2500, 256>>>(x, W1_0, W1_1, W1_2);
    k1b_kernel<<<2500, 256>>>(x, na, scW);
    // edge kernel: grid-stride over 640000 edges, 7 blocks/SM target
    k2_kernel<<<1036, 256>>>(ee, ea, eidx, Wm0, Wm1);
    k3_kernel<<<2500, 256>>>(l2_0, l2_1, l2_2, out);
    (void)in_sizes; (void)n_in; (void)out_size;
}

// round 2
// speedup vs baseline: 1.7905x; 1.7905x over previous
#include <cuda_runtime.h>

#define N_NODES 20000
#define N_EDGES 640000
#define EPB 4   // edges per warp iteration in k2

// ---------------- scratch (static device memory, no allocation) ----------------
__device__ float g_y0 [N_NODES * 32];        // y0[n][u]
__device__ float g_y1t[N_NODES * 3 * 32];    // y1t[n][m][u]
__device__ float g_y2t[N_NODES * 5 * 32];    // y2t[n][m][u]
__device__ float g_sc [3 * N_NODES * 32];    // sc[h][n][w]
__device__ float g_mid[N_NODES * 96];        // segment-summed messages

__device__ __forceinline__ float silu_f(float x) {
    return x / (1.0f + __expf(-x));
}

// packed f32x2 FMA: d = a*b + c (elementwise on 2 packed floats)
__device__ __forceinline__ unsigned long long fma2(unsigned long long a,
                                                   unsigned long long b,
                                                   unsigned long long c) {
    unsigned long long d;
    asm("fma.rn.f32x2 %0, %1, %2, %3;" : "=l"(d) : "l"(a), "l"(b), "l"(c));
    return d;
}
__device__ __forceinline__ float hsum2(unsigned long long a) {
    float lo, hi;
    asm("mov.b64 {%0, %1}, %2;" : "=f"(lo), "=f"(hi) : "l"(a));
    return lo + hi;
}

// ---------------- Kernel 1a: y0/y1/y2 node pre-linear, zero mid ----------------
__global__ void k1a_kernel(const float* __restrict__ x,
                           const float* __restrict__ W1_0,
                           const float* __restrict__ W1_1,
                           const float* __restrict__ W1_2)
{
    __shared__ __align__(16) float w0s[1024], w1s[1024], w2s[1024];
    int t = threadIdx.x;
    for (int i = t; i < 1024; i += blockDim.x) {
        w0s[i] = W1_0[i]; w1s[i] = W1_1[i]; w2s[i] = W1_2[i];
    }
    __syncthreads();

    int lane = t & 31;
    int n = (int)((blockIdx.x * blockDim.x + t) >> 5);
    if (n >= N_NODES) return;

    const float* xr = x + (size_t)n * 288;
    float x0r = xr[lane];
    float x1r[3], x2r[5];
#pragma unroll
    for (int m = 0; m < 3; m++) x1r[m] = xr[32 + lane * 3 + m];
#pragma unroll
    for (int m = 0; m < 5; m++) x2r[m] = xr[128 + lane * 5 + m];

    float a0 = 0.f;
    float a1[3] = {0.f, 0.f, 0.f};
    float a2[5] = {0.f, 0.f, 0.f, 0.f, 0.f};
#pragma unroll
    for (int u = 0; u < 32; u++) {
        float xv0 = __shfl_sync(0xffffffffu, x0r, u);
        a0 = fmaf(xv0, w0s[u * 32 + lane], a0);
#pragma unroll
        for (int m = 0; m < 3; m++) {
            float xv = __shfl_sync(0xffffffffu, x1r[m], u);
            a1[m] = fmaf(xv, w1s[u * 32 + lane], a1[m]);
        }
#pragma unroll
        for (int m = 0; m < 5; m++) {
            float xv = __shfl_sync(0xffffffffu, x2r[m], u);
            a2[m] = fmaf(xv, w2s[u * 32 + lane], a2[m]);
        }
    }
    const float inv = 0.17677669529663687f; // 1/sqrt(32)
    g_y0[n * 32 + lane] = a0 * inv;
#pragma unroll
    for (int m = 0; m < 3; m++) g_y1t[(n * 3 + m) * 32 + lane] = a1[m] * inv;
#pragma unroll
    for (int m = 0; m < 5; m++) g_y2t[(n * 5 + m) * 32 + lane] = a2[m] * inv;

    g_mid[n * 96 + lane]      = 0.f;
    g_mid[n * 96 + 32 + lane] = 0.f;
    g_mid[n * 96 + 64 + lane] = 0.f;
}

// ---------------- Kernel 1b: self-connection sc ----------------
__global__ void k1b_kernel(const float* __restrict__ x,
                           const float* __restrict__ na,
                           const float* __restrict__ scW)
{
    __shared__ __align__(16) float s[12288]; // 3*32*4*32 floats = 48KB
    int t = threadIdx.x;
    for (int i = t; i < 12288; i += blockDim.x) s[i] = scW[i];
    __syncthreads();

    int lane = t & 31;
    int n = (int)((blockIdx.x * blockDim.x + t) >> 5);
    if (n >= N_NODES) return;

    float x0r = x[(size_t)n * 288 + lane];
    float nar = (lane < 4) ? na[n * 4 + lane] : 0.f;
    float na0 = __shfl_sync(0xffffffffu, nar, 0);
    float na1 = __shfl_sync(0xffffffffu, nar, 1);
    float na2 = __shfl_sync(0xffffffffu, nar, 2);
    float na3 = __shfl_sync(0xffffffffu, nar, 3);

    float acc[3] = {0.f, 0.f, 0.f};
#pragma unroll
    for (int u = 0; u < 32; u++) {
        float x0u = __shfl_sync(0xffffffffu, x0r, u);
        float c0 = x0u * na0, c1 = x0u * na1, c2 = x0u * na2, c3 = x0u * na3;
#pragma unroll
        for (int h = 0; h < 3; h++) {
            const float* p = s + ((h * 32 + u) * 4) * 32 + lane;
            acc[h] = fmaf(c0, p[0],  acc[h]);
            acc[h] = fmaf(c1, p[32], acc[h]);
            acc[h] = fmaf(c2, p[64], acc[h]);
            acc[h] = fmaf(c3, p[96], acc[h]);
        }
    }
    const float invs = 0.08838834764831845f; // 1/sqrt(128)
#pragma unroll
    for (int h = 0; h < 3; h++)
        g_sc[h * (N_NODES * 32) + n * 32 + lane] = acc[h] * invs;
}

// ---------------- Kernel 2: fused edge MLP + gather + message + scatter ----------------
// warp processes EPB=4 edges per iteration; lane = output channel.
// h staged in smem (broadcast LDS instead of shuffles); Wm1 transposed in smem,
// read once per 4 edges; K-dim packed into fma.rn.f32x2.
__global__ void __launch_bounds__(256) k2_kernel(const float* __restrict__ ee,
                          const float* __restrict__ ea,
                          const int*   __restrict__ eidx,
                          const float* __restrict__ Wm0,
                          const float* __restrict__ Wm1)
{
    __shared__ __align__(16) float wm1t[96 * 68];      // [c][k], stride 68
    __shared__ __align__(16) float hbuf[8][EPB][64];   // per-warp h
    __shared__ __align__(16) float msgb[8][EPB][96];   // per-warp messages

    int t = threadIdx.x;
    for (int i = t; i < 64 * 96; i += blockDim.x) {
        int j = i / 96, c = i % 96;
        wm1t[c * 68 + j] = Wm1[i];
    }
    __syncthreads();

    int lane = t & 31;
    int wrp  = t >> 5;

    float wa[8], wb[8];
#pragma unroll
    for (int k = 0; k < 8; k++) {
        wa[k] = Wm0[k * 64 + lane];
        wb[k] = Wm0[k * 64 + 32 + lane];
    }

    const float inv8 = 0.35355339059327373f;  // 1/sqrt(8)
    const float C0 = 0.125f * 0.17677669529663687f;                        // invh*savg
    const float C1 = C0 * 0.5773502691896258f;                              // *1/sqrt3
    const float C2 = C0 * 0.4472135954999579f;                              // *1/sqrt5

    int warpid = blockIdx.x * 8 + wrp;
    int nwarp  = gridDim.x * 8;
    const int niter = N_EDGES / EPB;

    for (int it = warpid; it < niter; it += nwarp) {
        int ebase = it * EPB;
        int sidx[EPB], didx[EPB];
        float eav[EPB];
#pragma unroll
        for (int e = 0; e < EPB; e++) {
            sidx[e] = __ldg(&eidx[ebase + e]);
            didx[e] = __ldg(&eidx[N_EDGES + ebase + e]);
            float eev = (lane < 8) ? __ldg(&ee[(size_t)(ebase + e) * 8 + lane]) : 0.f;
            eav[e]    = (lane < 9) ? __ldg(&ea[(size_t)(ebase + e) * 9 + lane]) : 0.f;

            float ha = 0.f, hb = 0.f;
#pragma unroll
            for (int k = 0; k < 8; k++) {
                float ek = __shfl_sync(0xffffffffu, eev, k);
                ha = fmaf(ek, wa[k], ha);
                hb = fmaf(ek, wb[k], hb);
            }
            hbuf[wrp][e][lane]      = silu_f(ha * inv8);
            hbuf[wrp][e][32 + lane] = silu_f(hb * inv8);
        }
        __syncwarp();

        // ---- w = h @ Wm1 : f32x2-packed over K, weights reused across 4 edges ----
        unsigned long long A0[EPB], A1[EPB], A2[EPB];
#pragma unroll
        for (int e = 0; e < EPB; e++) { A0[e] = 0ull; A1[e] = 0ull; A2[e] = 0ull; }

        const float* w0p = &wm1t[lane * 68];
        const float* w1p = &wm1t[(32 + lane) * 68];
        const float* w2p = &wm1t[(64 + lane) * 68];
#pragma unroll
        for (int c = 0; c < 16; c++) {
            int k = c * 4;
            ulonglong2 q0 = *(const ulonglong2*)(w0p + k);
            ulonglong2 q1 = *(const ulonglong2*)(w1p + k);
            ulonglong2 q2 = *(const ulonglong2*)(w2p + k);
#pragma unroll
            for (int e = 0; e < EPB; e++) {
                ulonglong2 h = *(const ulonglong2*)&hbuf[wrp][e][k];
                A0[e] = fma2(h.x, q0.x, A0[e]);
                A0[e] = fma2(h.y, q0.y, A0[e]);
                A1[e] = fma2(h.x, q1.x, A1[e]);
                A1[e] = fma2(h.y, q1.y, A1[e]);
                A2[e] = fma2(h.x, q2.x, A2[e]);
                A2[e] = fma2(h.y, q2.y, A2[e]);
            }
        }
        __syncwarp();   // hbuf reads done before next-iteration writes

        // ---- per-edge gather + message ----
#pragma unroll
        for (int e = 0; e < EPB; e++) {
            float acc0 = hsum2(A0[e]);
            float acc1 = hsum2(A1[e]);
            float acc2 = hsum2(A2[e]);

            float y0v = g_y0[(size_t)sidx[e] * 32 + lane];
            float z1 = 0.f;
#pragma unroll
            for (int m = 0; m < 3; m++) {
                float Ym = __shfl_sync(0xffffffffu, eav[e], 1 + m);
                z1 = fmaf(Ym, g_y1t[((size_t)sidx[e] * 3 + m) * 32 + lane], z1);
            }
            float z2 = 0.f;
#pragma unroll
            for (int m = 0; m < 5; m++) {
                float Ym = __shfl_sync(0xffffffffu, eav[e], 4 + m);
                z2 = fmaf(Ym, g_y2t[((size_t)sidx[e] * 5 + m) * 32 + lane], z2);
            }
            float Y0 = __shfl_sync(0xffffffffu, eav[e], 0);

            msgb[wrp][e][lane]      = acc0 * C0 * y0v * Y0;
            msgb[wrp][e][32 + lane] = acc1 * C1 * z1;
            msgb[wrp][e][64 + lane] = acc2 * C2 * z2;
        }
        __syncwarp();

        // ---- vector atomic scatter ----
        if (lane < 24) {
#pragma unroll
            for (int e = 0; e < EPB; e++) {
                float4 v = *(const float4*)&msgb[wrp][e][lane * 4];
                float* p = &g_mid[(size_t)didx[e] * 96 + lane * 4];
                asm volatile("red.global.add.v4.f32 [%0], {%1,%2,%3,%4};"
                             :: "l"(p), "f"(v.x), "f"(v.y), "f"(v.z), "f"(v.w)
                             : "memory");
            }
        }
        __syncwarp();   // msgb consumed before next-iteration writes
    }
}

// ---------------- Kernel 3: node finalize (transposed weights + f32x2) ----------------
__global__ void k3_kernel(const float* __restrict__ l2_0,
                          const float* __restrict__ l2_1,
                          const float* __restrict__ l2_2,
                          float* __restrict__ out)
{
    __shared__ __align__(16) float s0t[32 * 36];   // [w][k], stride 36
    __shared__ __align__(16) float s1t[32 * 68];   // stride 68
    __shared__ __align__(16) float s2t[32 * 100];  // stride 100
    __shared__ __align__(16) float mb[8][96];

    int t = threadIdx.x;
    for (int i = t; i < 1024; i += blockDim.x) { int k = i / 32, w = i % 32; s0t[w * 36 + k]  = l2_0[i]; }
    for (int i = t; i < 2048; i += blockDim.x) { int k = i / 32, w = i % 32; s1t[w * 68 + k]  = l2_1[i]; }
    for (int i = t; i < 3072; i += blockDim.x) { int k = i / 32, w = i % 32; s2t[w * 100 + k] = l2_2[i]; }
    __syncthreads();

    int lane = t & 31;
    int wrp  = t >> 5;
    int n = (int)((blockIdx.x * blockDim.x + t) >> 5);
    if (n >= N_NODES) return;

    mb[wrp][lane]      = g_mid[n * 96 + lane];
    mb[wrp][32 + lane] = g_mid[n * 96 + 32 + lane];
    mb[wrp][64 + lane] = g_mid[n * 96 + 64 + lane];
    __syncwarp();

    unsigned long long A0 = 0ull, A1 = 0ull, A2 = 0ull;
    const float* p0 = &s0t[lane * 36];
    const float* p1 = &s1t[lane * 68];
    const float* p2 = &s2t[lane * 100];
#pragma unroll
    for (int c = 0; c < 24; c++) {
        int k = c * 4;
        ulonglong2 m4 = *(const ulonglong2*)&mb[wrp][k];
        ulonglong2 q2 = *(const ulonglong2*)(p2 + k);
        A2 = fma2(m4.x, q2.x, A2);
        A2 = fma2(m4.y, q2.y, A2);
        if (c < 16) {
            ulonglong2 q1 = *(const ulonglong2*)(p1 + k);
            A1 = fma2(m4.x, q1.x, A1);
            A1 = fma2(m4.y, q1.y, A1);
        }
        if (c < 8) {
            ulonglong2 q0 = *(const ulonglong2*)(p0 + k);
            A0 = fma2(m4.x, q0.x, A0);
            A0 = fma2(m4.y, q0.y, A0);
        }
    }

    const float i32 = 0.17677669529663687f;
    const float i64 = 0.125f;
    const float i96 = 0.10206207261596575f;

    float o0 = silu_f(fmaf(hsum2(A0), i32, g_sc[                   n * 32 + lane]));
    float o1 = silu_f(fmaf(hsum2(A1), i64, g_sc[N_NODES * 32     + n * 32 + lane]));
    float o2 = silu_f(fmaf(hsum2(A2), i96, g_sc[2 * N_NODES * 32 + n * 32 + lane]));

    out[                   n * 32 + lane] = o0;
    out[N_NODES * 32     + n * 32 + lane] = o1;
    out[2 * N_NODES * 32  + n * 32 + lane] = o2;
}

// ---------------- launch ----------------
extern "C" void kernel_launch(void* const* d_in, const int* in_sizes, int n_in,
                              void* d_out, int out_size)
{
    const float* x      = (const float*)d_in[0];
    const float* na     = (const float*)d_in[1];
    const float* ee     = (const float*)d_in[2];
    const float* ea     = (const float*)d_in[3];
    const int*   eidx   = (const int*)  d_in[4];
    const float* W1_0   = (const float*)d_in[5];
    const float* W1_1   = (const float*)d_in[6];
    const float* W1_2   = (const float*)d_in[7];
    const float* Wm0    = (const float*)d_in[8];
    const float* Wm1    = (const float*)d_in[9];
    const float* l2_0   = (const float*)d_in[10];
    const float* l2_1   = (const float*)d_in[11];
    const float* l2_2   = (const float*)d_in[12];
    const float* scW    = (const float*)d_in[13];
    float* out = (float*)d_out;

    k1a_kernel<<<2500, 256>>>(x, W1_0, W1_1, W1_2);
    k1b_kernel<<<2500, 256>>>(x, na, scW);
    k2_kernel<<<592, 256>>>(ee, ea, eidx, Wm0, Wm1);
    k3_kernel<<<2500, 256>>>(l2_0, l2_1, l2_2, out);
    (void)in_sizes; (void)n_in; (void)out_size;
}